// round 15
// baseline (speedup 1.0000x reference)
#include <cuda_runtime.h>
#include <cuda_bf16.h>
#include <cstdint>

#define SCALE_Q 0.10206207261596575f   // 1/sqrt(96)
#define XS 104   // bf16 row stride (96 cols + 8 pad)

// ---- smem: X hi/lo [64][104]x2 = 26624 (later V hi/lo)
//            K hi    [64][104]   = 13312
#define O_X  0
#define XLO2 13312
#define O_K  26624
#define SMEM_BYTES 39936

// W as pre-built MMA B-fragments: [chunk][k][ni][hi/lo][lane] (16B per lane)
__device__ __align__(16) uint4 g_wf[4][6][6][2][32];
__device__ __align__(8)  float g_cw[9][96];   // conv_w transposed [tap][ch]

__device__ __forceinline__ uint32_t smem_u32(const void* p) {
    uint32_t a;
    asm("{ .reg .u64 t; cvta.to.shared.u64 t, %1; cvt.u32.u64 %0, t; }" : "=r"(a) : "l"(p));
    return a;
}
__device__ __forceinline__ void ldm4(uint32_t a, uint32_t* r) {
    asm volatile("ldmatrix.sync.aligned.m8n8.x4.shared.b16 {%0,%1,%2,%3}, [%4];"
                 : "=r"(r[0]), "=r"(r[1]), "=r"(r[2]), "=r"(r[3]) : "r"(a));
}
__device__ __forceinline__ void ldm4t(uint32_t a, uint32_t* r) {
    asm volatile("ldmatrix.sync.aligned.m8n8.x4.trans.shared.b16 {%0,%1,%2,%3}, [%4];"
                 : "=r"(r[0]), "=r"(r[1]), "=r"(r[2]), "=r"(r[3]) : "r"(a));
}
#define MMA4(D, A, B0, B1) \
    asm volatile("mma.sync.aligned.m16n8k16.row.col.f32.bf16.bf16.f32 " \
        "{%0,%1,%2,%3},{%4,%5,%6,%7},{%8,%9},{%0,%1,%2,%3};" \
        : "+f"((D)[0]), "+f"((D)[1]), "+f"((D)[2]), "+f"((D)[3]) \
        : "r"((A)[0]), "r"((A)[1]), "r"((A)[2]), "r"((A)[3]), "r"(B0), "r"(B1))

// pack (a -> low half, b -> high half) with one cvt.rn.bf16x2.f32
__device__ __forceinline__ uint32_t bpack(float a, float b) {
    uint32_t r;
    asm("cvt.rn.bf16x2.f32 %0, %1, %2;" : "=r"(r) : "f"(b), "f"(a));
    return r;
}
// hi/lo split: h = packed bf16(a,b); residuals via bit reconstruction
__device__ __forceinline__ void split2(float a, float b, uint32_t& h, uint32_t& l) {
    h = bpack(a, b);
    float ra = a - __uint_as_float(h << 16);
    float rb = b - __uint_as_float(h & 0xffff0000u);
    l = bpack(ra, rb);
}

// ---- prep: build B-fragments (hi/lo) + transposed conv weights ----
__global__ void prep_w(const float* __restrict__ qkv_w, const float* __restrict__ out_w,
                       const float* __restrict__ conv_w) {
    int e = blockIdx.x * 256 + threadIdx.x;
    if (e < 4608) {                       // 4 chunks x 6 k x 6 ni x 32 lanes
        int lane = e & 31; int t = e >> 5;
        int ni = t % 6; t /= 6; int k = t % 6; int c = t / 6;
        const float* W = (c < 3 ? qkv_w + c * 9216 : out_w);
        int n0 = ni * 16 + (lane >> 2), n1 = n0 + 8;
        int kk = k * 16 + (lane & 3) * 2;
        uint32_t h0,l0,h1,l1,h2,l2,h3,l3;
        split2(W[n0*96+kk],   W[n0*96+kk+1], h0, l0);
        split2(W[n1*96+kk],   W[n1*96+kk+1], h1, l1);
        split2(W[n0*96+kk+8], W[n0*96+kk+9], h2, l2);
        split2(W[n1*96+kk+8], W[n1*96+kk+9], h3, l3);
        g_wf[c][k][ni][0][lane] = make_uint4(h0, h1, h2, h3);
        g_wf[c][k][ni][1][lane] = make_uint4(l0, l1, l2, l3);
    } else if (e < 4608 + 864) {
        int i = e - 4608;                 // conv_w [ch][tap] -> g_cw [tap][ch]
        int ch = i / 9, tap = i - ch * 9;
        g_cw[tap][ch] = conv_w[i];
    }
}

__global__ __launch_bounds__(128, 4)
void vitblock_mma(const float* __restrict__ x,
                  const float* __restrict__ qkv_b,
                  const float* __restrict__ conv_b,
                  const float* __restrict__ out_b,
                  float* __restrict__ out)
{
    extern __shared__ char smem[];
    const uint32_t sb = smem_u32(smem);
    const int tid = threadIdx.x;
    const int w = tid >> 5, lane = tid & 31;
    const int lr = lane & 15, lc = lane >> 4;
    const int c2 = (lane & 3) * 2;
    const int r0 = 16 * w + (lane >> 2);
    const int mw = w >> 1, nw = w & 1;    // 2x2 warp tiling for K/V GEMMs

    const int wv0 = blockIdx.x & 31;
    const int wh  = (blockIdx.x >> 5) & 31;
    const int bI  = blockIdx.x >> 10;
    const float* xg = x + ((size_t)bI * 96) * 65536 + (size_t)(wh * 8) * 256 + wv0 * 8;

    // ---- stage X hi/lo ----
    #pragma unroll
    for (int it = 0; it < 12; it++) {
        int e = it * 128 + tid;          // 1536 = 24 c4 x 64 tok
        int c4 = e >> 6, t = e & 63;
        const float* p = xg + (size_t)(c4 * 4) * 65536 + (t >> 3) * 256 + (t & 7);
        float v0 = p[0], v1 = p[65536], v2 = p[131072], v3 = p[196608];
        uint32_t h01, l01, h23, l23;
        split2(v0, v1, h01, l01);
        split2(v2, v3, h23, l23);
        uint2 H = { h01, h23 };
        uint2 L = { l01, l23 };
        uint32_t off = (uint32_t)(t * XS + c4 * 4) << 1;
        *(uint2*)(smem + O_X + off) = H;
        *(uint2*)(smem + O_X + XLO2 + off) = L;
    }
    __syncthreads();

    // ---- GEMM K (single-pass bf16, 2x2 warp tiling) ----
    {
        float dk[2][6][4];
        #pragma unroll
        for (int a = 0; a < 2; a++)
            #pragma unroll
            for (int j = 0; j < 6; j++) { dk[a][j][0]=0.f; dk[a][j][1]=0.f; dk[a][j][2]=0.f; dk[a][j][3]=0.f; }
        #pragma unroll
        for (int k = 0; k < 6; k++) {
            uint32_t ah[2][4];
            #pragma unroll
            for (int mi = 0; mi < 2; mi++)
                ldm4(sb + O_X + (((mw * 32 + mi * 16 + lr) * XS + k * 16 + lc * 8) << 1), ah[mi]);
            #pragma unroll
            for (int ni = 0; ni < 3; ni++) {
                uint4 BH = __ldg(&g_wf[1][k][nw * 3 + ni][0][lane]);
                #pragma unroll
                for (int mi = 0; mi < 2; mi++) {
                    MMA4(dk[mi][2*ni],   ah[mi], BH.x, BH.z);
                    MMA4(dk[mi][2*ni+1], ah[mi], BH.y, BH.w);
                }
            }
        }
        #pragma unroll
        for (int mi = 0; mi < 2; mi++)
            #pragma unroll
            for (int j = 0; j < 6; j++) {
                int col = nw * 48 + 8 * j + c2;
                float2 bk = __ldg((const float2*)(qkv_b + 96 + col));
                #pragma unroll
                for (int h = 0; h < 2; h++) {
                    int row = mw * 32 + mi * 16 + (lane >> 2) + 8 * h;
                    uint32_t hh = bpack(dk[mi][j][2*h] + bk.x, dk[mi][j][2*h+1] + bk.y);
                    *(uint32_t*)(smem + O_K + ((uint32_t)(row * XS + col) << 1)) = hh;
                }
            }
    }

    // ---- GEMM Q (single-pass bf16; fragments stay in registers) ----
    uint32_t qh[6][4];
    {
        float dq[12][4];
        #pragma unroll
        for (int j = 0; j < 12; j++) { dq[j][0]=0.f; dq[j][1]=0.f; dq[j][2]=0.f; dq[j][3]=0.f; }
        #pragma unroll
        for (int k = 0; k < 6; k++) {
            uint32_t ah[4];
            ldm4(sb + O_X + (((16 * w + lr) * XS + k * 16 + lc * 8) << 1), ah);
            #pragma unroll
            for (int ni = 0; ni < 6; ni++) {
                uint4 BH = __ldg(&g_wf[0][k][ni][0][lane]);
                MMA4(dq[2*ni],   ah, BH.x, BH.z);
                MMA4(dq[2*ni+1], ah, BH.y, BH.w);
            }
        }
        #pragma unroll
        for (int jj = 0; jj < 6; jj++) {
            int ta = 2 * jj, tb = 2 * jj + 1;
            float2 ba = __ldg((const float2*)(qkv_b + 8 * ta + c2));
            float2 bb = __ldg((const float2*)(qkv_b + 8 * tb + c2));
            qh[jj][0] = bpack((dq[ta][0] + ba.x) * SCALE_Q, (dq[ta][1] + ba.y) * SCALE_Q);
            qh[jj][1] = bpack((dq[ta][2] + ba.x) * SCALE_Q, (dq[ta][3] + ba.y) * SCALE_Q);
            qh[jj][2] = bpack((dq[tb][0] + bb.x) * SCALE_Q, (dq[tb][1] + bb.y) * SCALE_Q);
            qh[jj][3] = bpack((dq[tb][2] + bb.x) * SCALE_Q, (dq[tb][3] + bb.y) * SCALE_Q);
        }
    }

    // ---- GEMM V (3-term, 2x2 warp tiling; term-major -> dep distance 4) ----
    float dv[2][6][4];
    #pragma unroll
    for (int a = 0; a < 2; a++)
        #pragma unroll
        for (int j = 0; j < 6; j++) { dv[a][j][0]=0.f; dv[a][j][1]=0.f; dv[a][j][2]=0.f; dv[a][j][3]=0.f; }
    #pragma unroll
    for (int k = 0; k < 6; k++) {
        uint32_t ah[2][4], al[2][4];
        #pragma unroll
        for (int mi = 0; mi < 2; mi++) {
            uint32_t aa = sb + O_X + (((mw * 32 + mi * 16 + lr) * XS + k * 16 + lc * 8) << 1);
            ldm4(aa, ah[mi]);
            ldm4(aa + XLO2, al[mi]);
        }
        #pragma unroll
        for (int ni = 0; ni < 3; ni++) {
            uint4 BH = __ldg(&g_wf[2][k][nw * 3 + ni][0][lane]);
            uint4 BL = __ldg(&g_wf[2][k][nw * 3 + ni][1][lane]);
            // term hh
            MMA4(dv[0][2*ni],   ah[0], BH.x, BH.z);
            MMA4(dv[0][2*ni+1], ah[0], BH.y, BH.w);
            MMA4(dv[1][2*ni],   ah[1], BH.x, BH.z);
            MMA4(dv[1][2*ni+1], ah[1], BH.y, BH.w);
            // term hl
            MMA4(dv[0][2*ni],   ah[0], BL.x, BL.z);
            MMA4(dv[0][2*ni+1], ah[0], BL.y, BL.w);
            MMA4(dv[1][2*ni],   ah[1], BL.x, BL.z);
            MMA4(dv[1][2*ni+1], ah[1], BL.y, BL.w);
            // term lh
            MMA4(dv[0][2*ni],   al[0], BH.x, BH.z);
            MMA4(dv[0][2*ni+1], al[0], BH.y, BH.w);
            MMA4(dv[1][2*ni],   al[1], BH.x, BH.z);
            MMA4(dv[1][2*ni+1], al[1], BH.y, BH.w);
        }
    }
    __syncthreads();                    // all warps done reading X
    // write V hi/lo into X region (tok-major)
    #pragma unroll
    for (int mi = 0; mi < 2; mi++)
        #pragma unroll
        for (int j = 0; j < 6; j++) {
            int col = nw * 48 + 8 * j + c2;
            float2 bv = __ldg((const float2*)(qkv_b + 192 + col));
            #pragma unroll
            for (int h = 0; h < 2; h++) {
                int row = mw * 32 + mi * 16 + (lane >> 2) + 8 * h;
                uint32_t hh, ll;
                split2(dv[mi][j][2*h] + bv.x, dv[mi][j][2*h+1] + bv.y, hh, ll);
                uint32_t o0 = (uint32_t)(row * XS + col) << 1;
                *(uint32_t*)(smem + O_X + o0) = hh;
                *(uint32_t*)(smem + O_X + XLO2 + o0) = ll;
            }
        }
    __syncthreads();                    // V + K visible to all warps

    // ---- scores S = Q'K^T (single-pass bf16) ----
    float s[8][4];
    #pragma unroll
    for (int j = 0; j < 8; j++) { s[j][0]=0.f; s[j][1]=0.f; s[j][2]=0.f; s[j][3]=0.f; }
    #pragma unroll
    for (int k = 0; k < 6; k++) {
        #pragma unroll
        for (int np = 0; np < 4; np++) {
            uint32_t bh[4];
            ldm4(sb + O_K + (((np * 16 + lr) * XS + k * 16 + lc * 8) << 1), bh);
            MMA4(s[2*np],   qh[k], bh[0], bh[2]);
            MMA4(s[2*np+1], qh[k], bh[1], bh[3]);
        }
    }

    // ---- softmax in registers ----
    {
        float mx0 = -1e30f, mx1 = -1e30f;
        #pragma unroll
        for (int j = 0; j < 8; j++) {
            mx0 = fmaxf(mx0, fmaxf(s[j][0], s[j][1]));
            mx1 = fmaxf(mx1, fmaxf(s[j][2], s[j][3]));
        }
        mx0 = fmaxf(mx0, __shfl_xor_sync(0xffffffffu, mx0, 1));
        mx0 = fmaxf(mx0, __shfl_xor_sync(0xffffffffu, mx0, 2));
        mx1 = fmaxf(mx1, __shfl_xor_sync(0xffffffffu, mx1, 1));
        mx1 = fmaxf(mx1, __shfl_xor_sync(0xffffffffu, mx1, 2));
        float s0 = 0.f, s1 = 0.f;
        #pragma unroll
        for (int j = 0; j < 8; j++) {
            s[j][0] = __expf(s[j][0] - mx0); s[j][1] = __expf(s[j][1] - mx0);
            s[j][2] = __expf(s[j][2] - mx1); s[j][3] = __expf(s[j][3] - mx1);
            s0 += s[j][0] + s[j][1];
            s1 += s[j][2] + s[j][3];
        }
        s0 += __shfl_xor_sync(0xffffffffu, s0, 1);
        s0 += __shfl_xor_sync(0xffffffffu, s0, 2);
        s1 += __shfl_xor_sync(0xffffffffu, s1, 1);
        s1 += __shfl_xor_sync(0xffffffffu, s1, 2);
        float i0 = 1.0f / s0, i1 = 1.0f / s1;
        #pragma unroll
        for (int j = 0; j < 8; j++) {
            s[j][0] *= i0; s[j][1] *= i0; s[j][2] *= i1; s[j][3] *= i1;
        }
    }
    uint32_t ph[4][4], pl[4][4];
    #pragma unroll
    for (int jj = 0; jj < 4; jj++) {
        split2(s[2*jj][0],   s[2*jj][1],   ph[jj][0], pl[jj][0]);
        split2(s[2*jj][2],   s[2*jj][3],   ph[jj][1], pl[jj][1]);
        split2(s[2*jj+1][0], s[2*jj+1][1], ph[jj][2], pl[jj][2]);
        split2(s[2*jj+1][2], s[2*jj+1][3], ph[jj][3], pl[jj][3]);
    }

    // ---- PV: O = P @ V  (nb in pairs -> 4 accumulators, dep distance 4) ----
    float o[12][4];
    #pragma unroll
    for (int j = 0; j < 12; j++) { o[j][0]=0.f; o[j][1]=0.f; o[j][2]=0.f; o[j][3]=0.f; }
    {
        const int g = lane >> 3;
        const int tokoff = ((g >> 1) << 3) + (lane & 7);
        const int choff  = (g & 1) << 3;
        #pragma unroll
        for (int k = 0; k < 4; k++) {
            #pragma unroll
            for (int nbp = 0; nbp < 3; nbp++) {
                uint32_t bh0[4], bl0[4], bh1[4], bl1[4];
                uint32_t ba0 = sb + O_X + (((k * 16 + tokoff) * XS + (2*nbp) * 16 + choff) << 1);
                uint32_t ba1 = ba0 + (16 << 1);
                ldm4t(ba0, bh0);
                ldm4t(ba0 + XLO2, bl0);
                ldm4t(ba1, bh1);
                ldm4t(ba1 + XLO2, bl1);
                float* o0 = o[4*nbp];   float* o1 = o[4*nbp+1];
                float* o2 = o[4*nbp+2]; float* o3 = o[4*nbp+3];
                // term hh
                MMA4(o0, ph[k], bh0[0], bh0[2]);
                MMA4(o1, ph[k], bh0[1], bh0[3]);
                MMA4(o2, ph[k], bh1[0], bh1[2]);
                MMA4(o3, ph[k], bh1[1], bh1[3]);
                // term hl
                MMA4(o0, ph[k], bl0[0], bl0[2]);
                MMA4(o1, ph[k], bl0[1], bl0[3]);
                MMA4(o2, ph[k], bl1[0], bl1[2]);
                MMA4(o3, ph[k], bl1[1], bl1[3]);
                // term lh
                MMA4(o0, pl[k], bh0[0], bh0[2]);
                MMA4(o1, pl[k], bh0[1], bh0[3]);
                MMA4(o2, pl[k], bh1[0], bh1[2]);
                MMA4(o3, pl[k], bh1[1], bh1[3]);
            }
        }
    }

    // ---- O' = O + LePE + conv_b  (LePE uses V-hi plane ONLY) ----
    #pragma unroll
    for (int j = 0; j < 12; j++) {
        int c0 = 8 * j + c2;
        float2 cb2 = __ldg((const float2*)(conv_b + c0));
        float2 cw2[9];
        #pragma unroll
        for (int tap = 0; tap < 9; tap++)
            cw2[tap] = __ldg((const float2*)&g_cw[tap][c0]);
        #pragma unroll
        for (int h = 0; h < 2; h++) {
            int row = r0 + 8 * h;
            int y = row >> 3, xx = row & 7;
            float ax = o[j][2*h] + cb2.x, ay = o[j][2*h+1] + cb2.y;
            #pragma unroll
            for (int dy = -1; dy <= 1; dy++) {
                int yy = y + dy;
                if ((unsigned)yy > 7u) continue;
                #pragma unroll
                for (int dx = -1; dx <= 1; dx++) {
                    int xc = xx + dx;
                    if ((unsigned)xc > 7u) continue;
                    int nb = yy * 8 + xc;
                    uint32_t off = (uint32_t)(nb * XS + c0) << 1;
                    __nv_bfloat162 hv = *(__nv_bfloat162*)(smem + O_X + off);
                    float2 cw = cw2[(dy + 1) * 3 + (dx + 1)];
                    ax += __bfloat162float(hv.x) * cw.x;
                    ay += __bfloat162float(hv.y) * cw.y;
                }
            }
            o[j][2*h] = ax; o[j][2*h+1] = ay;
        }
    }

    // ---- pack O' to A-frags (hi/lo); o[] dead afterwards ----
    uint32_t oh[6][4], ol[6][4];
    #pragma unroll
    for (int jj = 0; jj < 6; jj++) {
        split2(o[2*jj][0],   o[2*jj][1],   oh[jj][0], ol[jj][0]);
        split2(o[2*jj][2],   o[2*jj][3],   oh[jj][1], ol[jj][1]);
        split2(o[2*jj+1][0], o[2*jj+1][1], oh[jj][2], ol[jj][2]);
        split2(o[2*jj+1][2], o[2*jj+1][3], oh[jj][3], ol[jj][3]);
    }

    // ---- GEMM3: ni in pairs (4 accumulators), direct global writeout ----
    float* og = out + (size_t)bI * 96 * 65536;
    const size_t pix0 = (size_t)((wh * 8 + 2 * w) * 256) + (size_t)(wv0 * 8 + (lane >> 2));
    #pragma unroll
    for (int nip = 0; nip < 3; nip++) {
        float f[4][4];
        #pragma unroll
        for (int q = 0; q < 4; q++) { f[q][0]=0.f; f[q][1]=0.f; f[q][2]=0.f; f[q][3]=0.f; }
        #pragma unroll
        for (int k = 0; k < 6; k++) {
            uint4 BH0 = __ldg(&g_wf[3][k][2*nip][0][lane]);
            uint4 BL0 = __ldg(&g_wf[3][k][2*nip][1][lane]);
            uint4 BH1 = __ldg(&g_wf[3][k][2*nip+1][0][lane]);
            uint4 BL1 = __ldg(&g_wf[3][k][2*nip+1][1][lane]);
            // term hh
            MMA4(f[0], oh[k], BH0.x, BH0.z);
            MMA4(f[1], oh[k], BH0.y, BH0.w);
            MMA4(f[2], oh[k], BH1.x, BH1.z);
            MMA4(f[3], oh[k], BH1.y, BH1.w);
            // term hl
            MMA4(f[0], oh[k], BL0.x, BL0.z);
            MMA4(f[1], oh[k], BL0.y, BL0.w);
            MMA4(f[2], oh[k], BL1.x, BL1.z);
            MMA4(f[3], oh[k], BL1.y, BL1.w);
            // term lh
            MMA4(f[0], ol[k], BH0.x, BH0.z);
            MMA4(f[1], ol[k], BH0.y, BH0.w);
            MMA4(f[2], ol[k], BH1.x, BH1.z);
            MMA4(f[3], ol[k], BH1.y, BH1.w);
        }
        #pragma unroll
        for (int q = 0; q < 4; q++) {
            int col = 32 * nip + 8 * q + c2;     // q = 2*(ni-2nip) + jj
            float2 bo = __ldg((const float2*)(out_b + col));
            float* p = og + (size_t)col * 65536 + pix0;
            p[0]            = f[q][0] + bo.x;   // row r0,   col
            p[65536]        = f[q][1] + bo.y;   // row r0,   col+1
            p[256]          = f[q][2] + bo.x;   // row r0+8, col
            p[65536 + 256]  = f[q][3] + bo.y;   // row r0+8, col+1
        }
    }
}

extern "C" void kernel_launch(void* const* d_in, const int* in_sizes, int n_in,
                              void* d_out, int out_size) {
    const float* x      = (const float*)d_in[0];
    const float* qkv_w  = (const float*)d_in[1];
    const float* qkv_b  = (const float*)d_in[2];
    const float* conv_w = (const float*)d_in[3];
    const float* conv_b = (const float*)d_in[4];
    const float* out_w  = (const float*)d_in[5];
    const float* out_b  = (const float*)d_in[6];
    float* out = (float*)d_out;

    prep_w<<<22, 256>>>(qkv_w, out_w, conv_w);
    cudaFuncSetAttribute(vitblock_mma,
                         cudaFuncAttributeMaxDynamicSharedMemorySize, SMEM_BYTES);
    vitblock_mma<<<8192, 128, SMEM_BYTES>>>(x, qkv_b, conv_b, out_b, out);
}

// round 16
// speedup vs baseline: 1.0186x; 1.0186x over previous
#include <cuda_runtime.h>
#include <cuda_bf16.h>
#include <cstdint>

#define SCALE_Q 0.10206207261596575f   // 1/sqrt(96)
#define XS 104   // bf16 row stride (96 cols + 8 pad)

// ---- smem: X hi/lo [64][104]x2 = 26624 (later V hi/lo)
//            K hi    [64][104]   = 13312
#define O_X  0
#define XLO2 13312
#define O_K  26624
#define SMEM_BYTES 39936

// W as pre-built MMA B-fragments: [chunk][k][ni][hi/lo][lane] (16B per lane)
__device__ __align__(16) uint4 g_wf[4][6][6][2][32];
__device__ __align__(8)  float g_cw[9][96];   // conv_w transposed [tap][ch]

__device__ __forceinline__ uint32_t smem_u32(const void* p) {
    uint32_t a;
    asm("{ .reg .u64 t; cvta.to.shared.u64 t, %1; cvt.u32.u64 %0, t; }" : "=r"(a) : "l"(p));
    return a;
}
__device__ __forceinline__ void ldm4(uint32_t a, uint32_t* r) {
    asm volatile("ldmatrix.sync.aligned.m8n8.x4.shared.b16 {%0,%1,%2,%3}, [%4];"
                 : "=r"(r[0]), "=r"(r[1]), "=r"(r[2]), "=r"(r[3]) : "r"(a));
}
__device__ __forceinline__ void ldm4t(uint32_t a, uint32_t* r) {
    asm volatile("ldmatrix.sync.aligned.m8n8.x4.trans.shared.b16 {%0,%1,%2,%3}, [%4];"
                 : "=r"(r[0]), "=r"(r[1]), "=r"(r[2]), "=r"(r[3]) : "r"(a));
}
#define MMA4(D, A, B0, B1) \
    asm volatile("mma.sync.aligned.m16n8k16.row.col.f32.bf16.bf16.f32 " \
        "{%0,%1,%2,%3},{%4,%5,%6,%7},{%8,%9},{%0,%1,%2,%3};" \
        : "+f"((D)[0]), "+f"((D)[1]), "+f"((D)[2]), "+f"((D)[3]) \
        : "r"((A)[0]), "r"((A)[1]), "r"((A)[2]), "r"((A)[3]), "r"(B0), "r"(B1))

// pack (a -> low half, b -> high half) with one cvt.rn.bf16x2.f32
__device__ __forceinline__ uint32_t bpack(float a, float b) {
    uint32_t r;
    asm("cvt.rn.bf16x2.f32 %0, %1, %2;" : "=r"(r) : "f"(b), "f"(a));
    return r;
}
// hi/lo split: h = packed bf16(a,b); residuals via bit reconstruction
__device__ __forceinline__ void split2(float a, float b, uint32_t& h, uint32_t& l) {
    h = bpack(a, b);
    float ra = a - __uint_as_float(h << 16);
    float rb = b - __uint_as_float(h & 0xffff0000u);
    l = bpack(ra, rb);
}

// ---- prep: build B-fragments (hi/lo) + transposed conv weights ----
__global__ void prep_w(const float* __restrict__ qkv_w, const float* __restrict__ out_w,
                       const float* __restrict__ conv_w) {
    int e = blockIdx.x * 256 + threadIdx.x;
    if (e < 4608) {                       // 4 chunks x 6 k x 6 ni x 32 lanes
        int lane = e & 31; int t = e >> 5;
        int ni = t % 6; t /= 6; int k = t % 6; int c = t / 6;
        const float* W = (c < 3 ? qkv_w + c * 9216 : out_w);
        int n0 = ni * 16 + (lane >> 2), n1 = n0 + 8;
        int kk = k * 16 + (lane & 3) * 2;
        uint32_t h0,l0,h1,l1,h2,l2,h3,l3;
        split2(W[n0*96+kk],   W[n0*96+kk+1], h0, l0);
        split2(W[n1*96+kk],   W[n1*96+kk+1], h1, l1);
        split2(W[n0*96+kk+8], W[n0*96+kk+9], h2, l2);
        split2(W[n1*96+kk+8], W[n1*96+kk+9], h3, l3);
        g_wf[c][k][ni][0][lane] = make_uint4(h0, h1, h2, h3);
        g_wf[c][k][ni][1][lane] = make_uint4(l0, l1, l2, l3);
    } else if (e < 4608 + 864) {
        int i = e - 4608;                 // conv_w [ch][tap] -> g_cw [tap][ch]
        int ch = i / 9, tap = i - ch * 9;
        g_cw[tap][ch] = conv_w[i];
    }
}

__global__ __launch_bounds__(128, 4)
void vitblock_mma(const float* __restrict__ x,
                  const float* __restrict__ qkv_b,
                  const float* __restrict__ conv_b,
                  const float* __restrict__ out_b,
                  float* __restrict__ out)
{
    extern __shared__ char smem[];
    const uint32_t sb = smem_u32(smem);
    const int tid = threadIdx.x;
    const int w = tid >> 5, lane = tid & 31;
    const int lr = lane & 15, lc = lane >> 4;
    const int c2 = (lane & 3) * 2;
    const int r0 = 16 * w + (lane >> 2);
    const int mw = w >> 1, nw = w & 1;    // 2x2 warp tiling for K/V GEMMs

    const int wv0 = blockIdx.x & 31;
    const int wh  = (blockIdx.x >> 5) & 31;
    const int bI  = blockIdx.x >> 10;
    const float* xg = x + ((size_t)bI * 96) * 65536 + (size_t)(wh * 8) * 256 + wv0 * 8;

    // ---- stage X hi/lo ----
    #pragma unroll
    for (int it = 0; it < 12; it++) {
        int e = it * 128 + tid;          // 1536 = 24 c4 x 64 tok
        int c4 = e >> 6, t = e & 63;
        const float* p = xg + (size_t)(c4 * 4) * 65536 + (t >> 3) * 256 + (t & 7);
        float v0 = p[0], v1 = p[65536], v2 = p[131072], v3 = p[196608];
        uint32_t h01, l01, h23, l23;
        split2(v0, v1, h01, l01);
        split2(v2, v3, h23, l23);
        uint2 H = { h01, h23 };
        uint2 L = { l01, l23 };
        uint32_t off = (uint32_t)(t * XS + c4 * 4) << 1;
        *(uint2*)(smem + O_X + off) = H;
        *(uint2*)(smem + O_X + XLO2 + off) = L;
    }
    __syncthreads();

    // ---- GEMM K (single-pass bf16, 2x2 warp tiling, A prefetch depth 1) ----
    {
        float dk[2][6][4];
        #pragma unroll
        for (int a = 0; a < 2; a++)
            #pragma unroll
            for (int j = 0; j < 6; j++) { dk[a][j][0]=0.f; dk[a][j][1]=0.f; dk[a][j][2]=0.f; dk[a][j][3]=0.f; }
        uint32_t ahb[2][2][4];
        #pragma unroll
        for (int mi = 0; mi < 2; mi++)
            ldm4(sb + O_X + (((mw * 32 + mi * 16 + lr) * XS + lc * 8) << 1), ahb[0][mi]);
        #pragma unroll
        for (int k = 0; k < 6; k++) {
            const int cur = k & 1;
            if (k < 5) {
                #pragma unroll
                for (int mi = 0; mi < 2; mi++)
                    ldm4(sb + O_X + (((mw * 32 + mi * 16 + lr) * XS + (k + 1) * 16 + lc * 8) << 1),
                         ahb[cur ^ 1][mi]);
            }
            #pragma unroll
            for (int ni = 0; ni < 3; ni++) {
                uint4 BH = __ldg(&g_wf[1][k][nw * 3 + ni][0][lane]);
                MMA4(dk[0][2*ni],   ahb[cur][0], BH.x, BH.z);
                MMA4(dk[0][2*ni+1], ahb[cur][0], BH.y, BH.w);
                MMA4(dk[1][2*ni],   ahb[cur][1], BH.x, BH.z);
                MMA4(dk[1][2*ni+1], ahb[cur][1], BH.y, BH.w);
            }
        }
        #pragma unroll
        for (int mi = 0; mi < 2; mi++)
            #pragma unroll
            for (int j = 0; j < 6; j++) {
                int col = nw * 48 + 8 * j + c2;
                float2 bk = __ldg((const float2*)(qkv_b + 96 + col));
                #pragma unroll
                for (int h = 0; h < 2; h++) {
                    int row = mw * 32 + mi * 16 + (lane >> 2) + 8 * h;
                    uint32_t hh = bpack(dk[mi][j][2*h] + bk.x, dk[mi][j][2*h+1] + bk.y);
                    *(uint32_t*)(smem + O_K + ((uint32_t)(row * XS + col) << 1)) = hh;
                }
            }
    }

    // ---- GEMM Q (single-pass bf16, A prefetch depth 1; fragments stay in regs) ----
    uint32_t qh[6][4];
    {
        float dq[12][4];
        #pragma unroll
        for (int j = 0; j < 12; j++) { dq[j][0]=0.f; dq[j][1]=0.f; dq[j][2]=0.f; dq[j][3]=0.f; }
        uint32_t ahb[2][4];
        ldm4(sb + O_X + (((16 * w + lr) * XS + lc * 8) << 1), ahb[0]);
        #pragma unroll
        for (int k = 0; k < 6; k++) {
            const int cur = k & 1;
            if (k < 5)
                ldm4(sb + O_X + (((16 * w + lr) * XS + (k + 1) * 16 + lc * 8) << 1), ahb[cur ^ 1]);
            #pragma unroll
            for (int ni = 0; ni < 6; ni++) {
                uint4 BH = __ldg(&g_wf[0][k][ni][0][lane]);
                MMA4(dq[2*ni],   ahb[cur], BH.x, BH.z);
                MMA4(dq[2*ni+1], ahb[cur], BH.y, BH.w);
            }
        }
        #pragma unroll
        for (int jj = 0; jj < 6; jj++) {
            int ta = 2 * jj, tb = 2 * jj + 1;
            float2 ba = __ldg((const float2*)(qkv_b + 8 * ta + c2));
            float2 bb = __ldg((const float2*)(qkv_b + 8 * tb + c2));
            qh[jj][0] = bpack((dq[ta][0] + ba.x) * SCALE_Q, (dq[ta][1] + ba.y) * SCALE_Q);
            qh[jj][1] = bpack((dq[ta][2] + ba.x) * SCALE_Q, (dq[ta][3] + ba.y) * SCALE_Q);
            qh[jj][2] = bpack((dq[tb][0] + bb.x) * SCALE_Q, (dq[tb][1] + bb.y) * SCALE_Q);
            qh[jj][3] = bpack((dq[tb][2] + bb.x) * SCALE_Q, (dq[tb][3] + bb.y) * SCALE_Q);
        }
    }

    // ---- GEMM V (3-term, 2x2 warp tiling, A prefetch depth 1) ----
    float dv[2][6][4];
    #pragma unroll
    for (int a = 0; a < 2; a++)
        #pragma unroll
        for (int j = 0; j < 6; j++) { dv[a][j][0]=0.f; dv[a][j][1]=0.f; dv[a][j][2]=0.f; dv[a][j][3]=0.f; }
    {
        uint32_t ahb[2][2][4], alb[2][2][4];
        #pragma unroll
        for (int mi = 0; mi < 2; mi++) {
            uint32_t aa = sb + O_X + (((mw * 32 + mi * 16 + lr) * XS + lc * 8) << 1);
            ldm4(aa, ahb[0][mi]);
            ldm4(aa + XLO2, alb[0][mi]);
        }
        #pragma unroll
        for (int k = 0; k < 6; k++) {
            const int cur = k & 1;
            if (k < 5) {
                #pragma unroll
                for (int mi = 0; mi < 2; mi++) {
                    uint32_t aa = sb + O_X + (((mw * 32 + mi * 16 + lr) * XS + (k + 1) * 16 + lc * 8) << 1);
                    ldm4(aa, ahb[cur ^ 1][mi]);
                    ldm4(aa + XLO2, alb[cur ^ 1][mi]);
                }
            }
            #pragma unroll
            for (int ni = 0; ni < 3; ni++) {
                uint4 BH = __ldg(&g_wf[2][k][nw * 3 + ni][0][lane]);
                uint4 BL = __ldg(&g_wf[2][k][nw * 3 + ni][1][lane]);
                // term hh
                MMA4(dv[0][2*ni],   ahb[cur][0], BH.x, BH.z);
                MMA4(dv[0][2*ni+1], ahb[cur][0], BH.y, BH.w);
                MMA4(dv[1][2*ni],   ahb[cur][1], BH.x, BH.z);
                MMA4(dv[1][2*ni+1], ahb[cur][1], BH.y, BH.w);
                // term hl
                MMA4(dv[0][2*ni],   ahb[cur][0], BL.x, BL.z);
                MMA4(dv[0][2*ni+1], ahb[cur][0], BL.y, BL.w);
                MMA4(dv[1][2*ni],   ahb[cur][1], BL.x, BL.z);
                MMA4(dv[1][2*ni+1], ahb[cur][1], BL.y, BL.w);
                // term lh
                MMA4(dv[0][2*ni],   alb[cur][0], BH.x, BH.z);
                MMA4(dv[0][2*ni+1], alb[cur][0], BH.y, BH.w);
                MMA4(dv[1][2*ni],   alb[cur][1], BH.x, BH.z);
                MMA4(dv[1][2*ni+1], alb[cur][1], BH.y, BH.w);
            }
        }
    }
    __syncthreads();                    // all warps done reading X
    // write V hi/lo into X region (tok-major)
    #pragma unroll
    for (int mi = 0; mi < 2; mi++)
        #pragma unroll
        for (int j = 0; j < 6; j++) {
            int col = nw * 48 + 8 * j + c2;
            float2 bv = __ldg((const float2*)(qkv_b + 192 + col));
            #pragma unroll
            for (int h = 0; h < 2; h++) {
                int row = mw * 32 + mi * 16 + (lane >> 2) + 8 * h;
                uint32_t hh, ll;
                split2(dv[mi][j][2*h] + bv.x, dv[mi][j][2*h+1] + bv.y, hh, ll);
                uint32_t o0 = (uint32_t)(row * XS + col) << 1;
                *(uint32_t*)(smem + O_X + o0) = hh;
                *(uint32_t*)(smem + O_X + XLO2 + o0) = ll;
            }
        }
    __syncthreads();                    // V + K visible to all warps

    // ---- scores S = Q'K^T (single-pass bf16, B prefetch depth 1) ----
    float s[8][4];
    #pragma unroll
    for (int j = 0; j < 8; j++) { s[j][0]=0.f; s[j][1]=0.f; s[j][2]=0.f; s[j][3]=0.f; }
    {
        uint32_t bhb[2][4];
        ldm4(sb + O_K + ((lr * XS + lc * 8) << 1), bhb[0]);
        #pragma unroll
        for (int k = 0; k < 6; k++) {
            #pragma unroll
            for (int np = 0; np < 4; np++) {
                const int idx = k * 4 + np;
                const int cur = idx & 1;
                if (idx < 23) {
                    const int nk = (idx + 1) >> 2, nnp = (idx + 1) & 3;
                    ldm4(sb + O_K + (((nnp * 16 + lr) * XS + nk * 16 + lc * 8) << 1), bhb[cur ^ 1]);
                }
                MMA4(s[2*np],   qh[k], bhb[cur][0], bhb[cur][2]);
                MMA4(s[2*np+1], qh[k], bhb[cur][1], bhb[cur][3]);
            }
        }
    }

    // ---- softmax in registers ----
    {
        float mx0 = -1e30f, mx1 = -1e30f;
        #pragma unroll
        for (int j = 0; j < 8; j++) {
            mx0 = fmaxf(mx0, fmaxf(s[j][0], s[j][1]));
            mx1 = fmaxf(mx1, fmaxf(s[j][2], s[j][3]));
        }
        mx0 = fmaxf(mx0, __shfl_xor_sync(0xffffffffu, mx0, 1));
        mx0 = fmaxf(mx0, __shfl_xor_sync(0xffffffffu, mx0, 2));
        mx1 = fmaxf(mx1, __shfl_xor_sync(0xffffffffu, mx1, 1));
        mx1 = fmaxf(mx1, __shfl_xor_sync(0xffffffffu, mx1, 2));
        float s0 = 0.f, s1 = 0.f;
        #pragma unroll
        for (int j = 0; j < 8; j++) {
            s[j][0] = __expf(s[j][0] - mx0); s[j][1] = __expf(s[j][1] - mx0);
            s[j][2] = __expf(s[j][2] - mx1); s[j][3] = __expf(s[j][3] - mx1);
            s0 += s[j][0] + s[j][1];
            s1 += s[j][2] + s[j][3];
        }
        s0 += __shfl_xor_sync(0xffffffffu, s0, 1);
        s0 += __shfl_xor_sync(0xffffffffu, s0, 2);
        s1 += __shfl_xor_sync(0xffffffffu, s1, 1);
        s1 += __shfl_xor_sync(0xffffffffu, s1, 2);
        float i0 = 1.0f / s0, i1 = 1.0f / s1;
        #pragma unroll
        for (int j = 0; j < 8; j++) {
            s[j][0] *= i0; s[j][1] *= i0; s[j][2] *= i1; s[j][3] *= i1;
        }
    }
    uint32_t ph[4][4], pl[4][4];
    #pragma unroll
    for (int jj = 0; jj < 4; jj++) {
        split2(s[2*jj][0],   s[2*jj][1],   ph[jj][0], pl[jj][0]);
        split2(s[2*jj][2],   s[2*jj][3],   ph[jj][1], pl[jj][1]);
        split2(s[2*jj+1][0], s[2*jj+1][1], ph[jj][2], pl[jj][2]);
        split2(s[2*jj+1][2], s[2*jj+1][3], ph[jj][3], pl[jj][3]);
    }

    // ---- PV: O = P @ V  (nb in pairs -> 4 accumulators) ----
    float o[12][4];
    #pragma unroll
    for (int j = 0; j < 12; j++) { o[j][0]=0.f; o[j][1]=0.f; o[j][2]=0.f; o[j][3]=0.f; }
    {
        const int g = lane >> 3;
        const int tokoff = ((g >> 1) << 3) + (lane & 7);
        const int choff  = (g & 1) << 3;
        #pragma unroll
        for (int k = 0; k < 4; k++) {
            #pragma unroll
            for (int nbp = 0; nbp < 3; nbp++) {
                uint32_t bh0[4], bl0[4], bh1[4], bl1[4];
                uint32_t ba0 = sb + O_X + (((k * 16 + tokoff) * XS + (2*nbp) * 16 + choff) << 1);
                uint32_t ba1 = ba0 + (16 << 1);
                ldm4t(ba0, bh0);
                ldm4t(ba0 + XLO2, bl0);
                ldm4t(ba1, bh1);
                ldm4t(ba1 + XLO2, bl1);
                float* o0 = o[4*nbp];   float* o1 = o[4*nbp+1];
                float* o2 = o[4*nbp+2]; float* o3 = o[4*nbp+3];
                // term hh
                MMA4(o0, ph[k], bh0[0], bh0[2]);
                MMA4(o1, ph[k], bh0[1], bh0[3]);
                MMA4(o2, ph[k], bh1[0], bh1[2]);
                MMA4(o3, ph[k], bh1[1], bh1[3]);
                // term hl
                MMA4(o0, ph[k], bl0[0], bl0[2]);
                MMA4(o1, ph[k], bl0[1], bl0[3]);
                MMA4(o2, ph[k], bl1[0], bl1[2]);
                MMA4(o3, ph[k], bl1[1], bl1[3]);
                // term lh
                MMA4(o0, pl[k], bh0[0], bh0[2]);
                MMA4(o1, pl[k], bh0[1], bh0[3]);
                MMA4(o2, pl[k], bh1[0], bh1[2]);
                MMA4(o3, pl[k], bh1[1], bh1[3]);
            }
        }
    }

    // ---- O' = O + LePE + conv_b  (LePE uses V-hi plane ONLY) ----
    #pragma unroll
    for (int j = 0; j < 12; j++) {
        int c0 = 8 * j + c2;
        float2 cb2 = __ldg((const float2*)(conv_b + c0));
        float2 cw2[9];
        #pragma unroll
        for (int tap = 0; tap < 9; tap++)
            cw2[tap] = __ldg((const float2*)&g_cw[tap][c0]);
        #pragma unroll
        for (int h = 0; h < 2; h++) {
            int row = r0 + 8 * h;
            int y = row >> 3, xx = row & 7;
            float ax = o[j][2*h] + cb2.x, ay = o[j][2*h+1] + cb2.y;
            #pragma unroll
            for (int dy = -1; dy <= 1; dy++) {
                int yy = y + dy;
                if ((unsigned)yy > 7u) continue;
                #pragma unroll
                for (int dx = -1; dx <= 1; dx++) {
                    int xc = xx + dx;
                    if ((unsigned)xc > 7u) continue;
                    int nb = yy * 8 + xc;
                    uint32_t off = (uint32_t)(nb * XS + c0) << 1;
                    __nv_bfloat162 hv = *(__nv_bfloat162*)(smem + O_X + off);
                    float2 cw = cw2[(dy + 1) * 3 + (dx + 1)];
                    ax += __bfloat162float(hv.x) * cw.x;
                    ay += __bfloat162float(hv.y) * cw.y;
                }
            }
            o[j][2*h] = ax; o[j][2*h+1] = ay;
        }
    }

    // ---- pack O' to A-frags (hi/lo); o[] dead afterwards ----
    uint32_t oh[6][4], ol[6][4];
    #pragma unroll
    for (int jj = 0; jj < 6; jj++) {
        split2(o[2*jj][0],   o[2*jj][1],   oh[jj][0], ol[jj][0]);
        split2(o[2*jj][2],   o[2*jj][3],   oh[jj][1], ol[jj][1]);
        split2(o[2*jj+1][0], o[2*jj+1][1], oh[jj][2], ol[jj][2]);
        split2(o[2*jj+1][2], o[2*jj+1][3], oh[jj][3], ol[jj][3]);
    }

    // ---- GEMM3: ni in pairs (4 accumulators), direct global writeout ----
    float* og = out + (size_t)bI * 96 * 65536;
    const size_t pix0 = (size_t)((wh * 8 + 2 * w) * 256) + (size_t)(wv0 * 8 + (lane >> 2));
    #pragma unroll
    for (int nip = 0; nip < 3; nip++) {
        float f[4][4];
        #pragma unroll
        for (int q = 0; q < 4; q++) { f[q][0]=0.f; f[q][1]=0.f; f[q][2]=0.f; f[q][3]=0.f; }
        #pragma unroll
        for (int k = 0; k < 6; k++) {
            uint4 BH0 = __ldg(&g_wf[3][k][2*nip][0][lane]);
            uint4 BL0 = __ldg(&g_wf[3][k][2*nip][1][lane]);
            uint4 BH1 = __ldg(&g_wf[3][k][2*nip+1][0][lane]);
            uint4 BL1 = __ldg(&g_wf[3][k][2*nip+1][1][lane]);
            // term hh
            MMA4(f[0], oh[k], BH0.x, BH0.z);
            MMA4(f[1], oh[k], BH0.y, BH0.w);
            MMA4(f[2], oh[k], BH1.x, BH1.z);
            MMA4(f[3], oh[k], BH1.y, BH1.w);
            // term hl
            MMA4(f[0], oh[k], BL0.x, BL0.z);
            MMA4(f[1], oh[k], BL0.y, BL0.w);
            MMA4(f[2], oh[k], BL1.x, BL1.z);
            MMA4(f[3], oh[k], BL1.y, BL1.w);
            // term lh
            MMA4(f[0], ol[k], BH0.x, BH0.z);
            MMA4(f[1], ol[k], BH0.y, BH0.w);
            MMA4(f[2], ol[k], BH1.x, BH1.z);
            MMA4(f[3], ol[k], BH1.y, BH1.w);
        }
        #pragma unroll
        for (int q = 0; q < 4; q++) {
            int col = 32 * nip + 8 * q + c2;     // q = 2*(ni-2nip) + jj
            float2 bo = __ldg((const float2*)(out_b + col));
            float* p = og + (size_t)col * 65536 + pix0;
            p[0]            = f[q][0] + bo.x;   // row r0,   col
            p[65536]        = f[q][1] + bo.y;   // row r0,   col+1
            p[256]          = f[q][2] + bo.x;   // row r0+8, col
            p[65536 + 256]  = f[q][3] + bo.y;   // row r0+8, col+1
        }
    }
}

extern "C" void kernel_launch(void* const* d_in, const int* in_sizes, int n_in,
                              void* d_out, int out_size) {
    const float* x      = (const float*)d_in[0];
    const float* qkv_w  = (const float*)d_in[1];
    const float* qkv_b  = (const float*)d_in[2];
    const float* conv_w = (const float*)d_in[3];
    const float* conv_b = (const float*)d_in[4];
    const float* out_w  = (const float*)d_in[5];
    const float* out_b  = (const float*)d_in[6];
    float* out = (float*)d_out;

    prep_w<<<22, 256>>>(qkv_w, out_w, conv_w);
    cudaFuncSetAttribute(vitblock_mma,
                         cudaFuncAttributeMaxDynamicSharedMemorySize, SMEM_BYTES);
    vitblock_mma<<<8192, 128, SMEM_BYTES>>>(x, qkv_b, conv_b, out_b, out);
}